// round 9
// baseline (speedup 1.0000x reference)
#include <cuda_runtime.h>
#include <stdint.h>

// ---------------------------------------------------------------------------
// Sparse average pooling — reference's effective semantics (int32 overflow
// drops the batch term): group/order by ascending lexicographic (q0,q1,q2).
//
// key = (q0<<18)|(q1<<9)|q2   (27 bits, q = coord>>1, coord in [0,1000))
// rank(key) = #distinct keys < key, via 2^27-bit occupancy bitmap (16 MB,
// L2-resident) + single-pass decoupled-lookback popcount prefix scan.
//
// Self-cleaning: k_scan re-zeroes the bitmap after reading it, k_finalize
// re-zeroes g_count, k_keys resets tile states + nfcount — so every
// invocation leaves device globals in the zero state the next one expects
// (globals start zero-initialized). No clear pass needed.
// ---------------------------------------------------------------------------

#define NWORDS  (1u << 22)           // 2^27 bits / 32
#define NTILES  4096                 // NWORDS / 1024 words per tile
#define MAXN    (1 << 20)

#define VMASK    0x3FFFFFFFu
#define PARTIAL  (1u << 30)
#define COMPLETE (2u << 30)

__device__ uint32_t g_bitmap[NWORDS];
__device__ uint2    g_wp[NWORDS];    // {exclusive word prefix, bitmap word}
__device__ uint32_t g_tilestate[NTILES];
__device__ uint32_t g_rankf[MAXN];   // rank | 0x80000000 if NOT first point
__device__ uint32_t g_count[MAXN];
__device__ uint32_t g_nflist[MAXN];
__device__ uint32_t g_nfcount;

__device__ __forceinline__ uint32_t warp_incl_scan(uint32_t v) {
    #pragma unroll
    for (int d = 1; d < 32; d <<= 1) {
        uint32_t nv = __shfl_up_sync(0xffffffffu, v, d);
        if ((threadIdx.x & 31) >= (unsigned)d) v += nv;
    }
    return v;
}

__device__ __forceinline__ uint32_t pack_key(int4 c) {
    return ((uint32_t)(c.x >> 1) << 18) | ((uint32_t)(c.y >> 1) << 9) |
            (uint32_t)(c.z >> 1);
}

// ---- pass 1: set occupancy bits; reset tile states + nfcount --------------
// Launched with exactly NTILES blocks (n <= MAXN = NTILES*256).

__global__ void k_keys(const int4* __restrict__ coords, int n) {
    if (threadIdx.x == 0) g_tilestate[blockIdx.x] = 0u;
    int i = blockIdx.x * blockDim.x + threadIdx.x;
    if (i == 0) g_nfcount = 0u;
    if (i >= n) return;
    uint32_t key = pack_key(coords[i]);
    atomicOr(&g_bitmap[key >> 5], 1u << (key & 31u));
}

// ---- pass 2: single-pass scan (decoupled lookback), build wp, re-zero bm --

__global__ void k_scan() {
    const uint4* bm4 = reinterpret_cast<const uint4*>(g_bitmap);
    const int tile = blockIdx.x;
    const int t = threadIdx.x;
    const uint32_t idx = tile * 256 + t;

    uint4 v = bm4[idx];
    uint32_t p0 = __popc(v.x), p1 = __popc(v.y), p2 = __popc(v.z), p3 = __popc(v.w);
    uint32_t s = p0 + p1 + p2 + p3;
    uint32_t incl = warp_incl_scan(s);

    __shared__ uint32_t wsum[8];
    __shared__ uint32_t s_base;
    int wid = t >> 5;
    if ((t & 31) == 31) wsum[wid] = incl;
    __syncthreads();

    if (t == 0) {
        uint32_t total = 0;
        #pragma unroll
        for (int j = 0; j < 8; j++) total += wsum[j];
        uint32_t base = 0;
        if (tile > 0) {
            atomicExch(&g_tilestate[tile], total | PARTIAL);
            int p = tile - 1;
            while (true) {
                uint32_t st = atomicAdd(&g_tilestate[p], 0u);
                uint32_t tag = st >> 30;
                if (tag == 2u) { base += st & VMASK; break; }
                if (tag == 1u) { base += st & VMASK; --p; }
            }
        }
        atomicExch(&g_tilestate[tile], (base + total) | COMPLETE);
        s_base = base;
    }
    __syncthreads();

    uint32_t wexcl = 0;
    for (int j = 0; j < wid; j++) wexcl += wsum[j];
    uint32_t b = s_base + wexcl + (incl - s);

    uint2* wp = g_wp + idx * 4;
    wp[0] = make_uint2(b, v.x);
    wp[1] = make_uint2(b + p0, v.y);
    wp[2] = make_uint2(b + p0 + p1, v.z);
    wp[3] = make_uint2(b + p0 + p1 + p2, v.w);

    // self-clean for the next invocation
    reinterpret_cast<uint4*>(g_bitmap)[idx] = make_uint4(0, 0, 0, 0);
}

// ---- pass 3: rank, counts, first-point coord stores -----------------------

__global__ void k_rank(const int4* __restrict__ coords,
                       float4* __restrict__ outC, int n) {
    int i = blockIdx.x * blockDim.x + threadIdx.x;
    if (i >= n) return;
    int4 c = coords[i];
    uint32_t key = pack_key(c);
    uint2 wp = g_wp[key >> 5];
    uint32_t rank = wp.x + __popc(wp.y & ((1u << (key & 31u)) - 1u));
    uint32_t old = atomicAdd(&g_count[rank], 1u);
    if (old == 0) {
        g_rankf[i] = rank;
        outC[rank] = make_float4((float)c.x, (float)c.y, (float)c.z, (float)c.w);
    } else {
        g_rankf[i] = rank | 0x80000000u;
        uint32_t pos = atomicAdd(&g_nfcount, 1u);
        g_nflist[pos] = i;
    }
}

// ---- pass 4: first-point feat copy (16 threads / point, float4) -----------

__global__ void k_featstore(const float4* __restrict__ feats4,
                            float4* __restrict__ outF4, int n) {
    int i = blockIdx.x * 16 + (threadIdx.x >> 4);
    int l = threadIdx.x & 15;
    if (i >= n) return;
    uint32_t r = g_rankf[i];
    float4 v = feats4[(size_t)i * 16 + l];
    if (!(r & 0x80000000u))
        outF4[(size_t)r * 16 + l] = v;
}

// ---- pass 5: residual (non-first) atomic adds (~8k points) ----------------

__global__ void k_residual(const int4* __restrict__ coords,
                           const float* __restrict__ feats,
                           float* __restrict__ outC, float* __restrict__ outF) {
    uint32_t cnt = g_nfcount;
    for (uint32_t idx = blockIdx.x * blockDim.x + threadIdx.x; idx < cnt;
         idx += gridDim.x * blockDim.x) {
        uint32_t i = g_nflist[idx];
        uint32_t r = g_rankf[i] & 0x7fffffffu;
        int4 c = coords[i];
        atomicAdd(&outC[(size_t)r * 4 + 0], (float)c.x);
        atomicAdd(&outC[(size_t)r * 4 + 1], (float)c.y);
        atomicAdd(&outC[(size_t)r * 4 + 2], (float)c.z);
        atomicAdd(&outC[(size_t)r * 4 + 3], (float)c.w);
        const float* f = feats + (size_t)i * 64;
        float* o = outF + (size_t)r * 64;
        #pragma unroll
        for (int d = 0; d < 64; d++) atomicAdd(&o[d], f[d]);
    }
}

// ---- pass 6: finalize — zero empty slots, divide multi slots, re-zero cnt -

__global__ void k_finalize(float* __restrict__ outC, float* __restrict__ outF,
                           int n) {
    int u = blockIdx.x * blockDim.x + threadIdx.x;
    if (u >= n) return;
    uint32_t c = g_count[u];
    g_count[u] = 0u;                        // self-clean for next invocation
    if (c == 1u) return;                    // singleton: already exact
    float4* oc = reinterpret_cast<float4*>(outC) + u;
    float4* of = reinterpret_cast<float4*>(outF) + (size_t)u * 16;
    if (c == 0u) {                          // empty padded slot -> zeros
        float4 z = make_float4(0.f, 0.f, 0.f, 0.f);
        *oc = z;
        #pragma unroll
        for (int j = 0; j < 16; j++) of[j] = z;
    } else {                                // divide; round-half-even coords
        float fc = (float)c;
        float4 v = *oc;
        v.x = rintf(v.x / fc); v.y = rintf(v.y / fc);
        v.z = rintf(v.z / fc); v.w = rintf(v.w / fc);
        *oc = v;
        #pragma unroll
        for (int j = 0; j < 16; j++) {
            float4 f = of[j];
            f.x /= fc; f.y /= fc; f.z /= fc; f.w /= fc;
            of[j] = f;
        }
    }
}

// ---------------------------------------------------------------------------

extern "C" void kernel_launch(void* const* d_in, const int* in_sizes, int n_in,
                              void* d_out, int out_size) {
    const int4*  coords = (const int4*)d_in[0];   // [N,4] int32
    const float* feats  = (const float*)d_in[1];  // [N,64] float32
    const int n = in_sizes[0] / 4;

    float* outC = (float*)d_out;                  // [N,4]
    float* outF = outC + (size_t)n * 4;           // [N,64]

    const int TPB = 256;
    const int nb = (n + TPB - 1) / TPB;

    // k_keys launched with NTILES blocks so every tile state is reset
    // (points guarded by i < n; n <= MAXN = NTILES*256).
    k_keys<<<NTILES, TPB>>>(coords, n);
    k_scan<<<NTILES, 256>>>();
    k_rank<<<nb, TPB>>>(coords, (float4*)outC, n);
    k_featstore<<<(n + 15) / 16, 256>>>((const float4*)feats, (float4*)outF, n);
    k_residual<<<64, 256>>>(coords, feats, outC, outF);
    k_finalize<<<nb, TPB>>>(outC, outF, n);
}

// round 10
// speedup vs baseline: 1.0258x; 1.0258x over previous
#include <cuda_runtime.h>
#include <stdint.h>

// ---------------------------------------------------------------------------
// Sparse average pooling — reference's effective semantics (int32 overflow
// drops the batch term): group/order by ascending lexicographic (q0,q1,q2).
//
// key = (q0<<18)|(q1<<9)|q2   (27 bits, q = coord>>1, coord in [0,1000))
// rank(key) = #distinct keys < key, via 2^27-bit occupancy bitmap (16 MB,
// L2-resident) + 3-kernel hierarchical popcount prefix (proven in R8).
//
// Self-cleaning (no clear pass): k_wordprefix zeroes bitmap words after
// final read, k_finalize zeroes g_count after read, k_keys resets nfcount.
// Globals start zero; every invocation restores the zero state.
// ---------------------------------------------------------------------------

#define NWORDS  (1u << 22)           // 2^27 bits / 32
#define NCHUNKS 1024                 // NWORDS / 4096 words per chunk
#define MAXN    (1 << 20)

__device__ uint32_t g_bitmap[NWORDS];
__device__ uint2    g_wp[NWORDS];    // {exclusive word prefix, bitmap word}
__device__ uint32_t g_chunksum[NCHUNKS];
__device__ uint32_t g_chunkprefix[NCHUNKS];
__device__ uint32_t g_count[MAXN];
__device__ uint2    g_nflist[MAXN];  // {point index, rank} of non-first points
__device__ uint32_t g_nfcount;

__device__ __forceinline__ uint32_t warp_incl_scan(uint32_t v) {
    #pragma unroll
    for (int d = 1; d < 32; d <<= 1) {
        uint32_t nv = __shfl_up_sync(0xffffffffu, v, d);
        if ((threadIdx.x & 31) >= (unsigned)d) v += nv;
    }
    return v;
}

__device__ __forceinline__ uint32_t pack_key(int4 c) {
    return ((uint32_t)(c.x >> 1) << 18) | ((uint32_t)(c.y >> 1) << 9) |
            (uint32_t)(c.z >> 1);
}

// ---- pass 1: set occupancy bits; reset nfcount ----------------------------

__global__ void k_keys(const int4* __restrict__ coords, int n) {
    int i = blockIdx.x * blockDim.x + threadIdx.x;
    if (i == 0) g_nfcount = 0u;
    if (i >= n) return;
    uint32_t key = pack_key(coords[i]);
    atomicOr(&g_bitmap[key >> 5], 1u << (key & 31u));
}

// ---- pass 2: per-chunk popcount sums (chunk = 4096 words) -----------------

__global__ void k_chunksum() {
    const uint4* bm4 = reinterpret_cast<const uint4*>(g_bitmap);
    uint32_t base = blockIdx.x * 1024 + threadIdx.x;   // uint4 index
    uint32_t s = 0;
    #pragma unroll
    for (int j = 0; j < 4; j++) {
        uint4 v = bm4[base + j * 256];
        s += __popc(v.x) + __popc(v.y) + __popc(v.z) + __popc(v.w);
    }
    s += __shfl_down_sync(0xffffffffu, s, 16);
    s += __shfl_down_sync(0xffffffffu, s, 8);
    s += __shfl_down_sync(0xffffffffu, s, 4);
    s += __shfl_down_sync(0xffffffffu, s, 2);
    s += __shfl_down_sync(0xffffffffu, s, 1);
    __shared__ uint32_t wsum[8];
    int wid = threadIdx.x >> 5;
    if ((threadIdx.x & 31) == 0) wsum[wid] = s;
    __syncthreads();
    if (threadIdx.x == 0) {
        uint32_t t = 0;
        #pragma unroll
        for (int j = 0; j < 8; j++) t += wsum[j];
        g_chunksum[blockIdx.x] = t;
    }
}

// ---- pass 3: exclusive scan of 1024 chunk sums (1 block, 1024 thr) --------

__global__ void k_chunkscan() {
    int t = threadIdx.x;
    uint32_t s = g_chunksum[t];
    uint32_t incl = warp_incl_scan(s);
    __shared__ uint32_t wsum[32];
    int wid = t >> 5;
    if ((t & 31) == 31) wsum[wid] = incl;
    __syncthreads();
    if (wid == 0) {
        uint32_t w = wsum[t & 31];
        w = warp_incl_scan(w);
        wsum[t & 31] = w;
    }
    __syncthreads();
    g_chunkprefix[t] = incl - s + (wid ? wsum[wid - 1] : 0u);
}

// ---- pass 4: fused {word prefix, word} table; self-clean bitmap -----------
// 1024 blocks x 1024 threads, one uint4 (4 words) per thread.

__global__ void k_wordprefix() {
    const int t = threadIdx.x;
    uint32_t idx = blockIdx.x * 1024 + t;              // uint4 index
    uint4 v = reinterpret_cast<const uint4*>(g_bitmap)[idx];
    uint32_t p0 = __popc(v.x), p1 = __popc(v.y), p2 = __popc(v.z), p3 = __popc(v.w);
    uint32_t s = p0 + p1 + p2 + p3;
    uint32_t incl = warp_incl_scan(s);
    __shared__ uint32_t wsum[32];
    int wid = t >> 5;
    if ((t & 31) == 31) wsum[wid] = incl;
    __syncthreads();
    if (wid == 0) {
        uint32_t w = wsum[t & 31];
        w = warp_incl_scan(w);
        wsum[t & 31] = w;
    }
    __syncthreads();
    uint32_t b = g_chunkprefix[blockIdx.x] + (wid ? wsum[wid - 1] : 0u) + (incl - s);
    uint2* wp = g_wp + idx * 4;
    wp[0] = make_uint2(b, v.x);
    wp[1] = make_uint2(b + p0, v.y);
    wp[2] = make_uint2(b + p0 + p1, v.z);
    wp[3] = make_uint2(b + p0 + p1 + p2, v.w);
    // self-clean for next invocation (last reader of the bitmap)
    reinterpret_cast<uint4*>(g_bitmap)[idx] = make_uint4(0, 0, 0, 0);
}

// ---- pass 5: fused rank + first-point coord/feat stores -------------------
// 16 lanes per point: lane 0 computes rank + does bookkeeping, then
// broadcasts; all lanes stream the 64-float feature row.

__global__ void k_rankfeat(const int4* __restrict__ coords,
                           const float4* __restrict__ feats4,
                           float4* __restrict__ outC,
                           float4* __restrict__ outF4, int n) {
    int i = blockIdx.x * 16 + (threadIdx.x >> 4);
    int lane = threadIdx.x & 15;
    if (i >= n) return;

    uint32_t rf = 0;
    if (lane == 0) {
        int4 c = coords[i];
        uint32_t key = pack_key(c);
        uint2 wp = g_wp[key >> 5];
        uint32_t rank = wp.x + __popc(wp.y & ((1u << (key & 31u)) - 1u));
        uint32_t old = atomicAdd(&g_count[rank], 1u);
        if (old == 0) {
            rf = rank;
            outC[rank] = make_float4((float)c.x, (float)c.y, (float)c.z, (float)c.w);
        } else {
            rf = rank | 0x80000000u;
            uint32_t pos = atomicAdd(&g_nfcount, 1u);
            g_nflist[pos] = make_uint2((uint32_t)i, rank);
        }
    }
    rf = __shfl_sync(0xffffffffu, rf, 0, 16);   // broadcast within 16-lane group

    float4 v = feats4[(size_t)i * 16 + lane];
    if (!(rf & 0x80000000u))
        outF4[(size_t)(rf & 0x7fffffffu) * 16 + lane] = v;
}

// ---- pass 6: residual (non-first) atomic adds (~8k points) ----------------

__global__ void k_residual(const int4* __restrict__ coords,
                           const float* __restrict__ feats,
                           float* __restrict__ outC, float* __restrict__ outF) {
    uint32_t cnt = g_nfcount;
    for (uint32_t idx = blockIdx.x * blockDim.x + threadIdx.x; idx < cnt;
         idx += gridDim.x * blockDim.x) {
        uint2 e = g_nflist[idx];
        uint32_t i = e.x, r = e.y;
        int4 c = coords[i];
        atomicAdd(&outC[(size_t)r * 4 + 0], (float)c.x);
        atomicAdd(&outC[(size_t)r * 4 + 1], (float)c.y);
        atomicAdd(&outC[(size_t)r * 4 + 2], (float)c.z);
        atomicAdd(&outC[(size_t)r * 4 + 3], (float)c.w);
        const float* f = feats + (size_t)i * 64;
        float* o = outF + (size_t)r * 64;
        #pragma unroll
        for (int d = 0; d < 64; d++) atomicAdd(&o[d], f[d]);
    }
}

// ---- pass 7: finalize — zero empty slots, divide multi slots, clean cnt ---

__global__ void k_finalize(float* __restrict__ outC, float* __restrict__ outF,
                           int n) {
    int u = blockIdx.x * blockDim.x + threadIdx.x;
    if (u >= n) return;
    uint32_t c = g_count[u];
    g_count[u] = 0u;                        // self-clean for next invocation
    if (c == 1u) return;                    // singleton: already exact
    float4* oc = reinterpret_cast<float4*>(outC) + u;
    float4* of = reinterpret_cast<float4*>(outF) + (size_t)u * 16;
    if (c == 0u) {                          // empty padded slot -> zeros
        float4 z = make_float4(0.f, 0.f, 0.f, 0.f);
        *oc = z;
        #pragma unroll
        for (int j = 0; j < 16; j++) of[j] = z;
    } else {                                // divide; round-half-even coords
        float fc = (float)c;
        float4 v = *oc;
        v.x = rintf(v.x / fc); v.y = rintf(v.y / fc);
        v.z = rintf(v.z / fc); v.w = rintf(v.w / fc);
        *oc = v;
        #pragma unroll
        for (int j = 0; j < 16; j++) {
            float4 f = of[j];
            f.x /= fc; f.y /= fc; f.z /= fc; f.w /= fc;
            of[j] = f;
        }
    }
}

// ---------------------------------------------------------------------------

extern "C" void kernel_launch(void* const* d_in, const int* in_sizes, int n_in,
                              void* d_out, int out_size) {
    const int4*  coords = (const int4*)d_in[0];   // [N,4] int32
    const float* feats  = (const float*)d_in[1];  // [N,64] float32
    const int n = in_sizes[0] / 4;

    float* outC = (float*)d_out;                  // [N,4]
    float* outF = outC + (size_t)n * 4;           // [N,64]

    const int TPB = 256;
    const int nb = (n + TPB - 1) / TPB;

    k_keys<<<nb, TPB>>>(coords, n);
    k_chunksum<<<NCHUNKS, 256>>>();
    k_chunkscan<<<1, 1024>>>();
    k_wordprefix<<<NCHUNKS, 1024>>>();
    k_rankfeat<<<(n + 15) / 16, 256>>>(coords, (const float4*)feats,
                                       (float4*)outC, (float4*)outF, n);
    k_residual<<<64, 256>>>(coords, feats, outC, outF);
    k_finalize<<<nb, TPB>>>(outC, outF, n);
}

// round 12
// speedup vs baseline: 1.1240x; 1.0957x over previous
#include <cuda_runtime.h>
#include <stdint.h>

// ---------------------------------------------------------------------------
// Sparse average pooling — reference's effective semantics (int32 overflow
// drops the batch term): group/order by ascending lexicographic (q0,q1,q2).
//
// key = (q0<<18)|(q1<<9)|q2   (27 bits, q = coord>>1, coord in [0,1000))
// rank(key) = #distinct keys < key, via 2^27-bit occupancy bitmap (16 MB,
// L2-resident) + 3-kernel hierarchical popcount prefix (R8-proven, exact).
//
// R12 == R11 rerun (R11 bench died with cudaErrorSystemNotReady in harness
// init — infra, kernel never ran). Change under test vs R8: k_rank and
// k_featstore fused into one kernel with a block-local smem handoff
// (phase 1: 1 point/thread rank computation; phase 2: 16-lane feature
// streaming). Each phase's memory access pattern is identical to its
// proven standalone kernel.
// ---------------------------------------------------------------------------

#define NWORDS  (1u << 22)           // 2^27 bits / 32
#define NCHUNKS 4096                 // NWORDS / 1024 words per chunk
#define MAXN    (1 << 20)

__device__ uint32_t g_bitmap[NWORDS];
__device__ uint32_t g_wordprefix[NWORDS];
__device__ uint32_t g_chunksum[NCHUNKS];
__device__ uint32_t g_chunkprefix[NCHUNKS];
__device__ uint32_t g_count[MAXN];
__device__ uint2    g_nflist[MAXN];  // {point index, rank} of non-first points
__device__ uint32_t g_nfcount;

__device__ __forceinline__ uint32_t warp_incl_scan(uint32_t v) {
    #pragma unroll
    for (int d = 1; d < 32; d <<= 1) {
        uint32_t nv = __shfl_up_sync(0xffffffffu, v, d);
        if ((threadIdx.x & 31) >= (unsigned)d) v += nv;
    }
    return v;
}

__device__ __forceinline__ uint32_t pack_key(int4 c) {
    return ((uint32_t)(c.x >> 1) << 18) | ((uint32_t)(c.y >> 1) << 9) |
            (uint32_t)(c.z >> 1);
}

// ---- pass 0: clear bitmap + counts (R8-exact) -----------------------------

__global__ void k_clear(int n) {
    uint32_t i = blockIdx.x * blockDim.x + threadIdx.x;   // 1M threads
    reinterpret_cast<uint4*>(g_bitmap)[i] = make_uint4(0, 0, 0, 0);
    if ((int)i < n) g_count[i] = 0;
    if (i == 0) g_nfcount = 0;
}

// ---- pass 1: set occupancy bits (R8-exact) --------------------------------

__global__ void k_keys(const int4* __restrict__ coords, int n) {
    int i = blockIdx.x * blockDim.x + threadIdx.x;
    if (i >= n) return;
    uint32_t key = pack_key(coords[i]);
    atomicOr(&g_bitmap[key >> 5], 1u << (key & 31u));
}

// ---- pass 2: per-chunk popcount sums (chunk = 1024 words, R8-exact) -------

__global__ void k_chunksum() {
    const uint4* bm4 = reinterpret_cast<const uint4*>(g_bitmap);
    uint4 v = bm4[blockIdx.x * 256 + threadIdx.x];
    uint32_t s = __popc(v.x) + __popc(v.y) + __popc(v.z) + __popc(v.w);
    s += __shfl_down_sync(0xffffffffu, s, 16);
    s += __shfl_down_sync(0xffffffffu, s, 8);
    s += __shfl_down_sync(0xffffffffu, s, 4);
    s += __shfl_down_sync(0xffffffffu, s, 2);
    s += __shfl_down_sync(0xffffffffu, s, 1);
    __shared__ uint32_t wsum[8];
    int wid = threadIdx.x >> 5;
    if ((threadIdx.x & 31) == 0) wsum[wid] = s;
    __syncthreads();
    if (threadIdx.x == 0) {
        uint32_t t = 0;
        #pragma unroll
        for (int j = 0; j < 8; j++) t += wsum[j];
        g_chunksum[blockIdx.x] = t;
    }
}

// ---- pass 3: exclusive scan of 4096 chunk sums (R8-exact) -----------------

__global__ void k_chunkscan() {
    int t = threadIdx.x;
    uint32_t local[4];
    uint32_t s = 0;
    #pragma unroll
    for (int j = 0; j < 4; j++) {
        local[j] = s;
        s += g_chunksum[t * 4 + j];
    }
    uint32_t incl = warp_incl_scan(s);
    __shared__ uint32_t wsum[32];
    int wid = t >> 5;
    if ((t & 31) == 31) wsum[wid] = incl;
    __syncthreads();
    if (wid == 0) {
        uint32_t w = wsum[t & 31];
        w = warp_incl_scan(w);
        wsum[t & 31] = w;
    }
    __syncthreads();
    uint32_t excl = incl - s + (wid ? wsum[wid - 1] : 0u);
    #pragma unroll
    for (int j = 0; j < 4; j++)
        g_chunkprefix[t * 4 + j] = excl + local[j];
}

// ---- pass 4: per-word global exclusive popcount prefix (R8-exact) ---------

__global__ void k_wordprefix() {
    const uint4* bm4 = reinterpret_cast<const uint4*>(g_bitmap);
    int t = threadIdx.x;
    uint32_t base_idx = blockIdx.x * 256 + t;
    uint4 v = bm4[base_idx];
    uint32_t p0 = __popc(v.x), p1 = __popc(v.y), p2 = __popc(v.z), p3 = __popc(v.w);
    uint32_t s = p0 + p1 + p2 + p3;
    uint32_t incl = warp_incl_scan(s);
    __shared__ uint32_t wsum[8];
    int wid = t >> 5;
    if ((t & 31) == 31) wsum[wid] = incl;
    __syncthreads();
    uint32_t wexcl = 0;
    for (int j = 0; j < wid; j++) wexcl += wsum[j];
    uint32_t base = g_chunkprefix[blockIdx.x] + wexcl + (incl - s);
    uint4 o;
    o.x = base;
    o.y = base + p0;
    o.z = base + p0 + p1;
    o.w = base + p0 + p1 + p2;
    reinterpret_cast<uint4*>(g_wordprefix)[base_idx] = o;
}

// ---- pass 5: fused rank + feature store -----------------------------------
// Phase 1: thread t ranks point base+t (identical pattern to R8 k_rank),
//          smem handoff. Phase 2: 16 lanes/point feature streaming
//          (identical pattern to R8 k_featstore).

__global__ void k_rankfeat(const int4* __restrict__ coords,
                           const float4* __restrict__ feats4,
                           float4* __restrict__ outC,
                           float4* __restrict__ outF4, int n) {
    __shared__ uint32_t srf[256];
    const int base = blockIdx.x * 256;
    const int t = threadIdx.x;
    const int i = base + t;

    if (i < n) {
        int4 c = coords[i];
        uint32_t key = pack_key(c);
        uint32_t w = key >> 5;
        uint32_t rank = g_wordprefix[w] +
                        __popc(g_bitmap[w] & ((1u << (key & 31u)) - 1u));
        uint32_t old = atomicAdd(&g_count[rank], 1u);
        if (old == 0) {
            srf[t] = rank;
            outC[rank] = make_float4((float)c.x, (float)c.y, (float)c.z, (float)c.w);
        } else {
            srf[t] = rank | 0x80000000u;
            uint32_t pos = atomicAdd(&g_nfcount, 1u);
            g_nflist[pos] = make_uint2((uint32_t)i, rank);
        }
    }
    __syncthreads();

    const int grp = t >> 4, lane = t & 15;
    #pragma unroll
    for (int j = 0; j < 16; j++) {
        int pl = j * 16 + grp;
        int gp = base + pl;
        if (gp < n) {
            uint32_t rf = srf[pl];
            float4 v = feats4[(size_t)gp * 16 + lane];
            if (!(rf & 0x80000000u))
                outF4[(size_t)(rf & 0x7fffffffu) * 16 + lane] = v;
        }
    }
}

// ---- pass 6: residual (non-first) atomic adds (~8k points) ----------------

__global__ void k_residual(const int4* __restrict__ coords,
                           const float* __restrict__ feats,
                           float* __restrict__ outC, float* __restrict__ outF) {
    uint32_t cnt = g_nfcount;
    for (uint32_t idx = blockIdx.x * blockDim.x + threadIdx.x; idx < cnt;
         idx += gridDim.x * blockDim.x) {
        uint2 e = g_nflist[idx];
        uint32_t i = e.x, r = e.y;
        int4 c = coords[i];
        atomicAdd(&outC[(size_t)r * 4 + 0], (float)c.x);
        atomicAdd(&outC[(size_t)r * 4 + 1], (float)c.y);
        atomicAdd(&outC[(size_t)r * 4 + 2], (float)c.z);
        atomicAdd(&outC[(size_t)r * 4 + 3], (float)c.w);
        const float* f = feats + (size_t)i * 64;
        float* o = outF + (size_t)r * 64;
        #pragma unroll
        for (int d = 0; d < 64; d++) atomicAdd(&o[d], f[d]);
    }
}

// ---- pass 7: finalize — zero empty slots, divide multi-point slots --------

__global__ void k_finalize(float* __restrict__ outC, float* __restrict__ outF,
                           int n) {
    int u = blockIdx.x * blockDim.x + threadIdx.x;
    if (u >= n) return;
    uint32_t c = g_count[u];
    if (c == 1u) return;                    // singleton: already exact
    float4* oc = reinterpret_cast<float4*>(outC) + u;
    float4* of = reinterpret_cast<float4*>(outF) + (size_t)u * 16;
    if (c == 0u) {                          // empty padded slot -> zeros
        float4 z = make_float4(0.f, 0.f, 0.f, 0.f);
        *oc = z;
        #pragma unroll
        for (int j = 0; j < 16; j++) of[j] = z;
    } else {                                // divide; round-half-even coords
        float fc = (float)c;
        float4 v = *oc;
        v.x = rintf(v.x / fc); v.y = rintf(v.y / fc);
        v.z = rintf(v.z / fc); v.w = rintf(v.w / fc);
        *oc = v;
        #pragma unroll
        for (int j = 0; j < 16; j++) {
            float4 f = of[j];
            f.x /= fc; f.y /= fc; f.z /= fc; f.w /= fc;
            of[j] = f;
        }
    }
}

// ---------------------------------------------------------------------------

extern "C" void kernel_launch(void* const* d_in, const int* in_sizes, int n_in,
                              void* d_out, int out_size) {
    const int4*  coords = (const int4*)d_in[0];   // [N,4] int32
    const float* feats  = (const float*)d_in[1];  // [N,64] float32
    const int n = in_sizes[0] / 4;

    float* outC = (float*)d_out;                  // [N,4]
    float* outF = outC + (size_t)n * 4;           // [N,64]

    const int TPB = 256;
    const int nb = (n + TPB - 1) / TPB;

    k_clear<<<NWORDS / 4 / TPB, TPB>>>(n);        // 1M threads
    k_keys<<<nb, TPB>>>(coords, n);
    k_chunksum<<<NCHUNKS, 256>>>();
    k_chunkscan<<<1, 1024>>>();
    k_wordprefix<<<NCHUNKS, 256>>>();
    k_rankfeat<<<nb, TPB>>>(coords, (const float4*)feats,
                            (float4*)outC, (float4*)outF, n);
    k_residual<<<64, 256>>>(coords, feats, outC, outF);
    k_finalize<<<nb, TPB>>>(outC, outF, n);
}

// round 13
// speedup vs baseline: 1.2145x; 1.0805x over previous
#include <cuda_runtime.h>
#include <stdint.h>

// ---------------------------------------------------------------------------
// Sparse average pooling — reference's effective semantics (int32 overflow
// drops the batch term): group/order by ascending lexicographic (q0,q1,q2).
//
// key = (q0<<18)|(q1<<9)|q2   (27 bits, q = coord>>1, coord in [0,1000))
// rank(key) = #distinct keys < key, via 2^27-bit occupancy bitmap (16 MB,
// L2-resident) + hierarchical popcount prefix.
//
// R13: the six scan-side launches (clear, keys, chunksum, chunkscan,
// wordprefix, rank) are consolidated into ONE persistent kernel (296 blocks,
// guaranteed co-resident at 2 blocks/SM) with software grid barriers between
// phases. Every phase's inner body is the R8-proven code verbatim.
// featstore / residual / finalize remain separate R8-exact launches.
//
// Grid barriers: per-barrier monotonic counters, never reset. Each arrival
// takes a ticket v and waits until the counter reaches
// (v/NBLK)*NBLK + NBLK — correct for any number of kernel invocations
// (correctness run + all graph replays), wrap-safe.
// ---------------------------------------------------------------------------

#define NWORDS  (1u << 22)           // 2^27 bits / 32
#define NCHUNKS 4096                 // NWORDS / 1024 words per chunk
#define MAXN    (1 << 20)
#define NBLK    296                  // 2 blocks/SM x 148 SMs: co-resident

__device__ uint32_t g_bitmap[NWORDS];
__device__ uint32_t g_wordprefix[NWORDS];
__device__ uint32_t g_chunksum[NCHUNKS];
__device__ uint32_t g_chunkprefix[NCHUNKS];
__device__ uint32_t g_rankf[MAXN];   // rank | 0x80000000 if NOT first point
__device__ uint32_t g_count[MAXN];
__device__ uint32_t g_nflist[MAXN];
__device__ uint32_t g_nfcount;
__device__ uint32_t g_barcnt[8];     // monotonic grid-barrier counters

__device__ __forceinline__ uint32_t warp_incl_scan(uint32_t v) {
    #pragma unroll
    for (int d = 1; d < 32; d <<= 1) {
        uint32_t nv = __shfl_up_sync(0xffffffffu, v, d);
        if ((threadIdx.x & 31) >= (unsigned)d) v += nv;
    }
    return v;
}

__device__ __forceinline__ uint32_t pack_key(int4 c) {
    return ((uint32_t)(c.x >> 1) << 18) | ((uint32_t)(c.y >> 1) << 9) |
            (uint32_t)(c.z >> 1);
}

// Monotonic software grid barrier (all NBLK blocks co-resident).
__device__ __forceinline__ void grid_bar(int b) {
    __syncthreads();
    if (threadIdx.x == 0) {
        __threadfence();
        uint32_t v = atomicAdd(&g_barcnt[b], 1u);
        uint32_t target = (v / NBLK) * NBLK + NBLK;
        while ((int32_t)(*(volatile uint32_t*)&g_barcnt[b] - target) < 0)
            __nanosleep(40);
        __threadfence();
    }
    __syncthreads();
}

// ---- persistent kernel: clear -> keys -> chunksum -> chunkscan ->
// ---- wordprefix -> rank, R8 bodies verbatim, block-stride partitioning ----

__global__ void __launch_bounds__(256, 2)
k_scanall(const int4* __restrict__ coords, float4* __restrict__ outC, int n) {
    const int tid = threadIdx.x;
    const uint32_t gsz = NBLK * 256;
    const uint32_t gt0 = blockIdx.x * 256 + tid;
    __shared__ uint32_t wsum[8];

    // phase 0: clear bitmap (1M uint4) + counts + nfcount
    for (uint32_t i = gt0; i < NWORDS / 4; i += gsz) {
        reinterpret_cast<uint4*>(g_bitmap)[i] = make_uint4(0, 0, 0, 0);
        if ((int)i < n) g_count[i] = 0;
    }
    if (gt0 == 0) g_nfcount = 0;
    grid_bar(0);

    // phase 1: set occupancy bits (R8 k_keys body)
    for (uint32_t i = gt0; i < (uint32_t)n; i += gsz) {
        uint32_t key = pack_key(coords[i]);
        atomicOr(&g_bitmap[key >> 5], 1u << (key & 31u));
    }
    grid_bar(1);

    // phase 2: per-chunk popcount sums (R8 k_chunksum body per chunk)
    const uint4* bm4 = reinterpret_cast<const uint4*>(g_bitmap);
    for (uint32_t c = blockIdx.x; c < NCHUNKS; c += NBLK) {
        uint4 v = bm4[c * 256 + tid];
        uint32_t s = __popc(v.x) + __popc(v.y) + __popc(v.z) + __popc(v.w);
        s += __shfl_down_sync(0xffffffffu, s, 16);
        s += __shfl_down_sync(0xffffffffu, s, 8);
        s += __shfl_down_sync(0xffffffffu, s, 4);
        s += __shfl_down_sync(0xffffffffu, s, 2);
        s += __shfl_down_sync(0xffffffffu, s, 1);
        int wid = tid >> 5;
        if ((tid & 31) == 0) wsum[wid] = s;
        __syncthreads();
        if (tid == 0) {
            uint32_t t = 0;
            #pragma unroll
            for (int j = 0; j < 8; j++) t += wsum[j];
            g_chunksum[c] = t;
        }
        __syncthreads();
    }
    grid_bar(2);

    // phase 3: exclusive scan of 4096 chunk sums (block 0, 16/thread)
    if (blockIdx.x == 0) {
        uint32_t local[16];
        uint32_t s = 0;
        #pragma unroll
        for (int j = 0; j < 16; j++) {
            local[j] = s;
            s += g_chunksum[tid * 16 + j];
        }
        uint32_t incl = warp_incl_scan(s);
        int wid = tid >> 5;
        if ((tid & 31) == 31) wsum[wid] = incl;
        __syncthreads();
        uint32_t wexcl = 0;
        for (int j = 0; j < wid; j++) wexcl += wsum[j];
        uint32_t excl = incl - s + wexcl;
        #pragma unroll
        for (int j = 0; j < 16; j++)
            g_chunkprefix[tid * 16 + j] = excl + local[j];
        __syncthreads();
    }
    grid_bar(3);

    // phase 4: per-word global exclusive popcount prefix (R8 body per chunk)
    for (uint32_t c = blockIdx.x; c < NCHUNKS; c += NBLK) {
        uint32_t base_idx = c * 256 + tid;
        uint4 v = bm4[base_idx];
        uint32_t p0 = __popc(v.x), p1 = __popc(v.y),
                 p2 = __popc(v.z), p3 = __popc(v.w);
        uint32_t s = p0 + p1 + p2 + p3;
        uint32_t incl = warp_incl_scan(s);
        int wid = tid >> 5;
        if ((tid & 31) == 31) wsum[wid] = incl;
        __syncthreads();
        uint32_t wexcl = 0;
        for (int j = 0; j < wid; j++) wexcl += wsum[j];
        uint32_t base = g_chunkprefix[c] + wexcl + (incl - s);
        uint4 o;
        o.x = base;
        o.y = base + p0;
        o.z = base + p0 + p1;
        o.w = base + p0 + p1 + p2;
        reinterpret_cast<uint4*>(g_wordprefix)[base_idx] = o;
        __syncthreads();
    }
    grid_bar(4);

    // phase 5: rank, counts, first-point coord stores (R8 k_rank body)
    for (uint32_t i = gt0; i < (uint32_t)n; i += gsz) {
        int4 c = coords[i];
        uint32_t key = pack_key(c);
        uint32_t w = key >> 5;
        uint32_t rank = g_wordprefix[w] +
                        __popc(g_bitmap[w] & ((1u << (key & 31u)) - 1u));
        uint32_t old = atomicAdd(&g_count[rank], 1u);
        if (old == 0) {
            g_rankf[i] = rank;
            outC[rank] = make_float4((float)c.x, (float)c.y, (float)c.z, (float)c.w);
        } else {
            g_rankf[i] = rank | 0x80000000u;
            uint32_t pos = atomicAdd(&g_nfcount, 1u);
            g_nflist[pos] = i;
        }
    }
}

// ---- first-point feat copy (R8-exact) -------------------------------------

__global__ void k_featstore(const float4* __restrict__ feats4,
                            float4* __restrict__ outF4, int n) {
    int i = blockIdx.x * 16 + (threadIdx.x >> 4);
    int l = threadIdx.x & 15;
    if (i >= n) return;
    uint32_t r = g_rankf[i];
    float4 v = feats4[(size_t)i * 16 + l];
    if (!(r & 0x80000000u))
        outF4[(size_t)r * 16 + l] = v;
}

// ---- residual (non-first) atomic adds (~8k points, R8-exact) --------------

__global__ void k_residual(const int4* __restrict__ coords,
                           const float* __restrict__ feats,
                           float* __restrict__ outC, float* __restrict__ outF) {
    uint32_t cnt = g_nfcount;
    for (uint32_t idx = blockIdx.x * blockDim.x + threadIdx.x; idx < cnt;
         idx += gridDim.x * blockDim.x) {
        uint32_t i = g_nflist[idx];
        uint32_t r = g_rankf[i] & 0x7fffffffu;
        int4 c = coords[i];
        atomicAdd(&outC[(size_t)r * 4 + 0], (float)c.x);
        atomicAdd(&outC[(size_t)r * 4 + 1], (float)c.y);
        atomicAdd(&outC[(size_t)r * 4 + 2], (float)c.z);
        atomicAdd(&outC[(size_t)r * 4 + 3], (float)c.w);
        const float* f = feats + (size_t)i * 64;
        float* o = outF + (size_t)r * 64;
        #pragma unroll
        for (int d = 0; d < 64; d++) atomicAdd(&o[d], f[d]);
    }
}

// ---- finalize — zero empty slots, divide multi-point slots (R8-exact) -----

__global__ void k_finalize(float* __restrict__ outC, float* __restrict__ outF,
                           int n) {
    int u = blockIdx.x * blockDim.x + threadIdx.x;
    if (u >= n) return;
    uint32_t c = g_count[u];
    if (c == 1u) return;                    // singleton: already exact
    float4* oc = reinterpret_cast<float4*>(outC) + u;
    float4* of = reinterpret_cast<float4*>(outF) + (size_t)u * 16;
    if (c == 0u) {                          // empty padded slot -> zeros
        float4 z = make_float4(0.f, 0.f, 0.f, 0.f);
        *oc = z;
        #pragma unroll
        for (int j = 0; j < 16; j++) of[j] = z;
    } else {                                // divide; round-half-even coords
        float fc = (float)c;
        float4 v = *oc;
        v.x = rintf(v.x / fc); v.y = rintf(v.y / fc);
        v.z = rintf(v.z / fc); v.w = rintf(v.w / fc);
        *oc = v;
        #pragma unroll
        for (int j = 0; j < 16; j++) {
            float4 f = of[j];
            f.x /= fc; f.y /= fc; f.z /= fc; f.w /= fc;
            of[j] = f;
        }
    }
}

// ---------------------------------------------------------------------------

extern "C" void kernel_launch(void* const* d_in, const int* in_sizes, int n_in,
                              void* d_out, int out_size) {
    const int4*  coords = (const int4*)d_in[0];   // [N,4] int32
    const float* feats  = (const float*)d_in[1];  // [N,64] float32
    const int n = in_sizes[0] / 4;

    float* outC = (float*)d_out;                  // [N,4]
    float* outF = outC + (size_t)n * 4;           // [N,64]

    const int TPB = 256;
    const int nb = (n + TPB - 1) / TPB;

    k_scanall<<<NBLK, TPB>>>(coords, (float4*)outC, n);
    k_featstore<<<(n + 15) / 16, 256>>>((const float4*)feats, (float4*)outF, n);
    k_residual<<<64, 256>>>(coords, feats, outC, outF);
    k_finalize<<<nb, TPB>>>(outC, outF, n);
}

// round 14
// speedup vs baseline: 1.4444x; 1.1893x over previous
#include <cuda_runtime.h>
#include <stdint.h>

// ---------------------------------------------------------------------------
// Sparse average pooling — reference's effective semantics (int32 overflow
// drops the batch term): group/order by ascending lexicographic (q0,q1,q2).
//
// key = (q0<<18)|(q1<<9)|q2   (27 bits, q = coord>>1, coord in [0,1000))
// rank(key) = #distinct keys < key, via 2^27-bit occupancy bitmap (16 MB,
// L2-resident) + hierarchical popcount prefix.
//
// R14 vs R13: counts are final at the end of the persistent kernel, so a new
// phase 6 compacts the ~8k slots with count != 1 into a worklist; k_finalize
// then processes ONLY those slots with 16 lanes each (R13's finalize burned
// 64 us single-lane-divergent over 1M slots at 1% DRAM).
// ---------------------------------------------------------------------------

#define NWORDS  (1u << 22)           // 2^27 bits / 32
#define NCHUNKS 4096                 // NWORDS / 1024 words per chunk
#define MAXN    (1 << 20)
#define NBLK    296                  // 2 blocks/SM x 148 SMs: co-resident

__device__ uint32_t g_bitmap[NWORDS];
__device__ uint32_t g_wordprefix[NWORDS];
__device__ uint32_t g_chunksum[NCHUNKS];
__device__ uint32_t g_chunkprefix[NCHUNKS];
__device__ uint32_t g_rankf[MAXN];   // rank | 0x80000000 if NOT first point
__device__ uint32_t g_count[MAXN];
__device__ uint32_t g_nflist[MAXN];
__device__ uint32_t g_nfcount;
__device__ uint2    g_wl[MAXN];      // {slot, count} for slots with count != 1
__device__ uint32_t g_wlcount;
__device__ uint32_t g_barcnt[8];     // monotonic grid-barrier counters

__device__ __forceinline__ uint32_t warp_incl_scan(uint32_t v) {
    #pragma unroll
    for (int d = 1; d < 32; d <<= 1) {
        uint32_t nv = __shfl_up_sync(0xffffffffu, v, d);
        if ((threadIdx.x & 31) >= (unsigned)d) v += nv;
    }
    return v;
}

__device__ __forceinline__ uint32_t pack_key(int4 c) {
    return ((uint32_t)(c.x >> 1) << 18) | ((uint32_t)(c.y >> 1) << 9) |
            (uint32_t)(c.z >> 1);
}

// Monotonic software grid barrier (all NBLK blocks co-resident).
__device__ __forceinline__ void grid_bar(int b) {
    __syncthreads();
    if (threadIdx.x == 0) {
        __threadfence();
        uint32_t v = atomicAdd(&g_barcnt[b], 1u);
        uint32_t target = (v / NBLK) * NBLK + NBLK;
        while ((int32_t)(*(volatile uint32_t*)&g_barcnt[b] - target) < 0)
            __nanosleep(40);
        __threadfence();
    }
    __syncthreads();
}

// ---- persistent kernel: clear -> keys -> chunksum -> chunkscan ->
// ---- wordprefix -> rank -> compact-worklist -------------------------------

__global__ void __launch_bounds__(256, 2)
k_scanall(const int4* __restrict__ coords, float4* __restrict__ outC, int n) {
    const int tid = threadIdx.x;
    const uint32_t gsz = NBLK * 256;
    const uint32_t gt0 = blockIdx.x * 256 + tid;
    __shared__ uint32_t wsum[8];

    // phase 0: clear bitmap (1M uint4) + counts + counters
    for (uint32_t i = gt0; i < NWORDS / 4; i += gsz) {
        reinterpret_cast<uint4*>(g_bitmap)[i] = make_uint4(0, 0, 0, 0);
        if ((int)i < n) g_count[i] = 0;
    }
    if (gt0 == 0) { g_nfcount = 0; g_wlcount = 0; }
    grid_bar(0);

    // phase 1: set occupancy bits
    for (uint32_t i = gt0; i < (uint32_t)n; i += gsz) {
        uint32_t key = pack_key(coords[i]);
        atomicOr(&g_bitmap[key >> 5], 1u << (key & 31u));
    }
    grid_bar(1);

    // phase 2: per-chunk popcount sums
    const uint4* bm4 = reinterpret_cast<const uint4*>(g_bitmap);
    for (uint32_t c = blockIdx.x; c < NCHUNKS; c += NBLK) {
        uint4 v = bm4[c * 256 + tid];
        uint32_t s = __popc(v.x) + __popc(v.y) + __popc(v.z) + __popc(v.w);
        s += __shfl_down_sync(0xffffffffu, s, 16);
        s += __shfl_down_sync(0xffffffffu, s, 8);
        s += __shfl_down_sync(0xffffffffu, s, 4);
        s += __shfl_down_sync(0xffffffffu, s, 2);
        s += __shfl_down_sync(0xffffffffu, s, 1);
        int wid = tid >> 5;
        if ((tid & 31) == 0) wsum[wid] = s;
        __syncthreads();
        if (tid == 0) {
            uint32_t t = 0;
            #pragma unroll
            for (int j = 0; j < 8; j++) t += wsum[j];
            g_chunksum[c] = t;
        }
        __syncthreads();
    }
    grid_bar(2);

    // phase 3: exclusive scan of 4096 chunk sums (block 0, 16/thread)
    if (blockIdx.x == 0) {
        uint32_t local[16];
        uint32_t s = 0;
        #pragma unroll
        for (int j = 0; j < 16; j++) {
            local[j] = s;
            s += g_chunksum[tid * 16 + j];
        }
        uint32_t incl = warp_incl_scan(s);
        int wid = tid >> 5;
        if ((tid & 31) == 31) wsum[wid] = incl;
        __syncthreads();
        uint32_t wexcl = 0;
        for (int j = 0; j < wid; j++) wexcl += wsum[j];
        uint32_t excl = incl - s + wexcl;
        #pragma unroll
        for (int j = 0; j < 16; j++)
            g_chunkprefix[tid * 16 + j] = excl + local[j];
        __syncthreads();
    }
    grid_bar(3);

    // phase 4: per-word global exclusive popcount prefix
    for (uint32_t c = blockIdx.x; c < NCHUNKS; c += NBLK) {
        uint32_t base_idx = c * 256 + tid;
        uint4 v = bm4[base_idx];
        uint32_t p0 = __popc(v.x), p1 = __popc(v.y),
                 p2 = __popc(v.z), p3 = __popc(v.w);
        uint32_t s = p0 + p1 + p2 + p3;
        uint32_t incl = warp_incl_scan(s);
        int wid = tid >> 5;
        if ((tid & 31) == 31) wsum[wid] = incl;
        __syncthreads();
        uint32_t wexcl = 0;
        for (int j = 0; j < wid; j++) wexcl += wsum[j];
        uint32_t base = g_chunkprefix[c] + wexcl + (incl - s);
        uint4 o;
        o.x = base;
        o.y = base + p0;
        o.z = base + p0 + p1;
        o.w = base + p0 + p1 + p2;
        reinterpret_cast<uint4*>(g_wordprefix)[base_idx] = o;
        __syncthreads();
    }
    grid_bar(4);

    // phase 5: rank, counts, first-point coord stores
    for (uint32_t i = gt0; i < (uint32_t)n; i += gsz) {
        int4 c = coords[i];
        uint32_t key = pack_key(c);
        uint32_t w = key >> 5;
        uint32_t rank = g_wordprefix[w] +
                        __popc(g_bitmap[w] & ((1u << (key & 31u)) - 1u));
        uint32_t old = atomicAdd(&g_count[rank], 1u);
        if (old == 0) {
            g_rankf[i] = rank;
            outC[rank] = make_float4((float)c.x, (float)c.y, (float)c.z, (float)c.w);
        } else {
            g_rankf[i] = rank | 0x80000000u;
            uint32_t pos = atomicAdd(&g_nfcount, 1u);
            g_nflist[pos] = i;
        }
    }
    grid_bar(5);

    // phase 6: compact slots with count != 1 into the finalize worklist
    for (uint32_t u = gt0; u < (uint32_t)n; u += gsz) {
        uint32_t c = g_count[u];
        if (c != 1u) {
            uint32_t pos = atomicAdd(&g_wlcount, 1u);
            g_wl[pos] = make_uint2(u, c);
        }
    }
}

// ---- first-point feat copy (R8-exact) -------------------------------------

__global__ void k_featstore(const float4* __restrict__ feats4,
                            float4* __restrict__ outF4, int n) {
    int i = blockIdx.x * 16 + (threadIdx.x >> 4);
    int l = threadIdx.x & 15;
    if (i >= n) return;
    uint32_t r = g_rankf[i];
    float4 v = feats4[(size_t)i * 16 + l];
    if (!(r & 0x80000000u))
        outF4[(size_t)r * 16 + l] = v;
}

// ---- residual (non-first) atomic adds (~8k points, R8-exact) --------------

__global__ void k_residual(const int4* __restrict__ coords,
                           const float* __restrict__ feats,
                           float* __restrict__ outC, float* __restrict__ outF) {
    uint32_t cnt = g_nfcount;
    for (uint32_t idx = blockIdx.x * blockDim.x + threadIdx.x; idx < cnt;
         idx += gridDim.x * blockDim.x) {
        uint32_t i = g_nflist[idx];
        uint32_t r = g_rankf[i] & 0x7fffffffu;
        int4 c = coords[i];
        atomicAdd(&outC[(size_t)r * 4 + 0], (float)c.x);
        atomicAdd(&outC[(size_t)r * 4 + 1], (float)c.y);
        atomicAdd(&outC[(size_t)r * 4 + 2], (float)c.z);
        atomicAdd(&outC[(size_t)r * 4 + 3], (float)c.w);
        const float* f = feats + (size_t)i * 64;
        float* o = outF + (size_t)r * 64;
        #pragma unroll
        for (int d = 0; d < 64; d++) atomicAdd(&o[d], f[d]);
    }
}

// ---- finalize — worklist-driven, 16 lanes per slot ------------------------

__global__ void k_finalize(float4* __restrict__ outC,
                           float4* __restrict__ outF4) {
    uint32_t cnt = g_wlcount;
    uint32_t ngroups = (gridDim.x * blockDim.x) >> 4;
    uint32_t grp = (blockIdx.x * blockDim.x + threadIdx.x) >> 4;
    uint32_t lane = threadIdx.x & 15;

    for (uint32_t g = grp; g < cnt; g += ngroups) {
        uint2 e = g_wl[g];
        uint32_t u = e.x, c = e.y;
        float4* of = outF4 + (size_t)u * 16;
        if (c == 0u) {                      // empty padded slot -> zeros
            of[lane] = make_float4(0.f, 0.f, 0.f, 0.f);
            if (lane == 0) outC[u] = make_float4(0.f, 0.f, 0.f, 0.f);
        } else {                            // divide; round-half-even coords
            float fc = (float)c;
            float4 f = of[lane];
            f.x /= fc; f.y /= fc; f.z /= fc; f.w /= fc;
            of[lane] = f;
            if (lane == 0) {
                float4 v = outC[u];
                v.x = rintf(v.x / fc); v.y = rintf(v.y / fc);
                v.z = rintf(v.z / fc); v.w = rintf(v.w / fc);
                outC[u] = v;
            }
        }
    }
}

// ---------------------------------------------------------------------------

extern "C" void kernel_launch(void* const* d_in, const int* in_sizes, int n_in,
                              void* d_out, int out_size) {
    const int4*  coords = (const int4*)d_in[0];   // [N,4] int32
    const float* feats  = (const float*)d_in[1];  // [N,64] float32
    const int n = in_sizes[0] / 4;

    float* outC = (float*)d_out;                  // [N,4]
    float* outF = outC + (size_t)n * 4;           // [N,64]

    const int TPB = 256;

    k_scanall<<<NBLK, TPB>>>(coords, (float4*)outC, n);
    k_featstore<<<(n + 15) / 16, 256>>>((const float4*)feats, (float4*)outF, n);
    k_residual<<<64, 256>>>(coords, feats, outC, outF);
    k_finalize<<<128, 256>>>((float4*)outC, (float4*)outF);
}

// round 16
// speedup vs baseline: 1.5333x; 1.0615x over previous
#include <cuda_runtime.h>
#include <stdint.h>

// ---------------------------------------------------------------------------
// Sparse average pooling — reference's effective semantics (int32 overflow
// drops the batch term): group/order by ascending lexicographic (q0,q1,q2).
//
// key = (q0<<18)|(q1<<9)|q2   (27 bits, q = coord>>1, coord in [0,1000))
// rank(key) = #distinct keys < key, via 2^27-bit occupancy bitmap (16 MB,
// L2-resident) + hierarchical popcount prefix, in ONE persistent kernel
// with monotonic grid barriers (R13/R14-proven).
//
// R15 vs R14: NBLK 296 -> 592 (4 co-resident blocks/SM via
// __launch_bounds__(256,4)) to double latency hiding in the scattered-L2
// phases (1 and 5), and finalize grid 128 -> 512. No other changes.
// ---------------------------------------------------------------------------

#define NWORDS  (1u << 22)           // 2^27 bits / 32
#define NCHUNKS 4096                 // NWORDS / 1024 words per chunk
#define MAXN    (1 << 20)
#define NBLK    592                  // 4 blocks/SM x 148 SMs: co-resident

__device__ uint32_t g_bitmap[NWORDS];
__device__ uint32_t g_wordprefix[NWORDS];
__device__ uint32_t g_chunksum[NCHUNKS];
__device__ uint32_t g_chunkprefix[NCHUNKS];
__device__ uint32_t g_rankf[MAXN];   // rank | 0x80000000 if NOT first point
__device__ uint32_t g_count[MAXN];
__device__ uint32_t g_nflist[MAXN];
__device__ uint32_t g_nfcount;
__device__ uint2    g_wl[MAXN];      // {slot, count} for slots with count != 1
__device__ uint32_t g_wlcount;
__device__ uint32_t g_barcnt[8];     // monotonic grid-barrier counters

__device__ __forceinline__ uint32_t warp_incl_scan(uint32_t v) {
    #pragma unroll
    for (int d = 1; d < 32; d <<= 1) {
        uint32_t nv = __shfl_up_sync(0xffffffffu, v, d);
        if ((threadIdx.x & 31) >= (unsigned)d) v += nv;
    }
    return v;
}

__device__ __forceinline__ uint32_t pack_key(int4 c) {
    return ((uint32_t)(c.x >> 1) << 18) | ((uint32_t)(c.y >> 1) << 9) |
            (uint32_t)(c.z >> 1);
}

// Monotonic software grid barrier (all NBLK blocks co-resident).
__device__ __forceinline__ void grid_bar(int b) {
    __syncthreads();
    if (threadIdx.x == 0) {
        __threadfence();
        uint32_t v = atomicAdd(&g_barcnt[b], 1u);
        uint32_t target = (v / NBLK) * NBLK + NBLK;
        while ((int32_t)(*(volatile uint32_t*)&g_barcnt[b] - target) < 0)
            __nanosleep(40);
        __threadfence();
    }
    __syncthreads();
}

// ---- persistent kernel: clear -> keys -> chunksum -> chunkscan ->
// ---- wordprefix -> rank -> compact-worklist -------------------------------

__global__ void __launch_bounds__(256, 4)
k_scanall(const int4* __restrict__ coords, float4* __restrict__ outC, int n) {
    const int tid = threadIdx.x;
    const uint32_t gsz = NBLK * 256;
    const uint32_t gt0 = blockIdx.x * 256 + tid;
    __shared__ uint32_t wsum[8];

    // phase 0: clear bitmap (1M uint4) + counts + counters
    for (uint32_t i = gt0; i < NWORDS / 4; i += gsz) {
        reinterpret_cast<uint4*>(g_bitmap)[i] = make_uint4(0, 0, 0, 0);
        if ((int)i < n) g_count[i] = 0;
    }
    if (gt0 == 0) { g_nfcount = 0; g_wlcount = 0; }
    grid_bar(0);

    // phase 1: set occupancy bits
    for (uint32_t i = gt0; i < (uint32_t)n; i += gsz) {
        uint32_t key = pack_key(coords[i]);
        atomicOr(&g_bitmap[key >> 5], 1u << (key & 31u));
    }
    grid_bar(1);

    // phase 2: per-chunk popcount sums
    const uint4* bm4 = reinterpret_cast<const uint4*>(g_bitmap);
    for (uint32_t c = blockIdx.x; c < NCHUNKS; c += NBLK) {
        uint4 v = bm4[c * 256 + tid];
        uint32_t s = __popc(v.x) + __popc(v.y) + __popc(v.z) + __popc(v.w);
        s += __shfl_down_sync(0xffffffffu, s, 16);
        s += __shfl_down_sync(0xffffffffu, s, 8);
        s += __shfl_down_sync(0xffffffffu, s, 4);
        s += __shfl_down_sync(0xffffffffu, s, 2);
        s += __shfl_down_sync(0xffffffffu, s, 1);
        int wid = tid >> 5;
        if ((tid & 31) == 0) wsum[wid] = s;
        __syncthreads();
        if (tid == 0) {
            uint32_t t = 0;
            #pragma unroll
            for (int j = 0; j < 8; j++) t += wsum[j];
            g_chunksum[c] = t;
        }
        __syncthreads();
    }
    grid_bar(2);

    // phase 3: exclusive scan of 4096 chunk sums (block 0, 16/thread)
    if (blockIdx.x == 0) {
        uint32_t local[16];
        uint32_t s = 0;
        #pragma unroll
        for (int j = 0; j < 16; j++) {
            local[j] = s;
            s += g_chunksum[tid * 16 + j];
        }
        uint32_t incl = warp_incl_scan(s);
        int wid = tid >> 5;
        if ((tid & 31) == 31) wsum[wid] = incl;
        __syncthreads();
        uint32_t wexcl = 0;
        for (int j = 0; j < wid; j++) wexcl += wsum[j];
        uint32_t excl = incl - s + wexcl;
        #pragma unroll
        for (int j = 0; j < 16; j++)
            g_chunkprefix[tid * 16 + j] = excl + local[j];
        __syncthreads();
    }
    grid_bar(3);

    // phase 4: per-word global exclusive popcount prefix
    for (uint32_t c = blockIdx.x; c < NCHUNKS; c += NBLK) {
        uint32_t base_idx = c * 256 + tid;
        uint4 v = bm4[base_idx];
        uint32_t p0 = __popc(v.x), p1 = __popc(v.y),
                 p2 = __popc(v.z), p3 = __popc(v.w);
        uint32_t s = p0 + p1 + p2 + p3;
        uint32_t incl = warp_incl_scan(s);
        int wid = tid >> 5;
        if ((tid & 31) == 31) wsum[wid] = incl;
        __syncthreads();
        uint32_t wexcl = 0;
        for (int j = 0; j < wid; j++) wexcl += wsum[j];
        uint32_t base = g_chunkprefix[c] + wexcl + (incl - s);
        uint4 o;
        o.x = base;
        o.y = base + p0;
        o.z = base + p0 + p1;
        o.w = base + p0 + p1 + p2;
        reinterpret_cast<uint4*>(g_wordprefix)[base_idx] = o;
        __syncthreads();
    }
    grid_bar(4);

    // phase 5: rank, counts, first-point coord stores
    for (uint32_t i = gt0; i < (uint32_t)n; i += gsz) {
        int4 c = coords[i];
        uint32_t key = pack_key(c);
        uint32_t w = key >> 5;
        uint32_t rank = g_wordprefix[w] +
                        __popc(g_bitmap[w] & ((1u << (key & 31u)) - 1u));
        uint32_t old = atomicAdd(&g_count[rank], 1u);
        if (old == 0) {
            g_rankf[i] = rank;
            outC[rank] = make_float4((float)c.x, (float)c.y, (float)c.z, (float)c.w);
        } else {
            g_rankf[i] = rank | 0x80000000u;
            uint32_t pos = atomicAdd(&g_nfcount, 1u);
            g_nflist[pos] = i;
        }
    }
    grid_bar(5);

    // phase 6: compact slots with count != 1 into the finalize worklist
    for (uint32_t u = gt0; u < (uint32_t)n; u += gsz) {
        uint32_t c = g_count[u];
        if (c != 1u) {
            uint32_t pos = atomicAdd(&g_wlcount, 1u);
            g_wl[pos] = make_uint2(u, c);
        }
    }
}

// ---- first-point feat copy (R8-exact) -------------------------------------

__global__ void k_featstore(const float4* __restrict__ feats4,
                            float4* __restrict__ outF4, int n) {
    int i = blockIdx.x * 16 + (threadIdx.x >> 4);
    int l = threadIdx.x & 15;
    if (i >= n) return;
    uint32_t r = g_rankf[i];
    float4 v = feats4[(size_t)i * 16 + l];
    if (!(r & 0x80000000u))
        outF4[(size_t)r * 16 + l] = v;
}

// ---- residual (non-first) atomic adds (~8k points, R8-exact) --------------

__global__ void k_residual(const int4* __restrict__ coords,
                           const float* __restrict__ feats,
                           float* __restrict__ outC, float* __restrict__ outF) {
    uint32_t cnt = g_nfcount;
    for (uint32_t idx = blockIdx.x * blockDim.x + threadIdx.x; idx < cnt;
         idx += gridDim.x * blockDim.x) {
        uint32_t i = g_nflist[idx];
        uint32_t r = g_rankf[i] & 0x7fffffffu;
        int4 c = coords[i];
        atomicAdd(&outC[(size_t)r * 4 + 0], (float)c.x);
        atomicAdd(&outC[(size_t)r * 4 + 1], (float)c.y);
        atomicAdd(&outC[(size_t)r * 4 + 2], (float)c.z);
        atomicAdd(&outC[(size_t)r * 4 + 3], (float)c.w);
        const float* f = feats + (size_t)i * 64;
        float* o = outF + (size_t)r * 64;
        #pragma unroll
        for (int d = 0; d < 64; d++) atomicAdd(&o[d], f[d]);
    }
}

// ---- finalize — worklist-driven, 16 lanes per slot ------------------------

__global__ void k_finalize(float4* __restrict__ outC,
                           float4* __restrict__ outF4) {
    uint32_t cnt = g_wlcount;
    uint32_t ngroups = (gridDim.x * blockDim.x) >> 4;
    uint32_t grp = (blockIdx.x * blockDim.x + threadIdx.x) >> 4;
    uint32_t lane = threadIdx.x & 15;

    for (uint32_t g = grp; g < cnt; g += ngroups) {
        uint2 e = g_wl[g];
        uint32_t u = e.x, c = e.y;
        float4* of = outF4 + (size_t)u * 16;
        if (c == 0u) {                      // empty padded slot -> zeros
            of[lane] = make_float4(0.f, 0.f, 0.f, 0.f);
            if (lane == 0) outC[u] = make_float4(0.f, 0.f, 0.f, 0.f);
        } else {                            // divide; round-half-even coords
            float fc = (float)c;
            float4 f = of[lane];
            f.x /= fc; f.y /= fc; f.z /= fc; f.w /= fc;
            of[lane] = f;
            if (lane == 0) {
                float4 v = outC[u];
                v.x = rintf(v.x / fc); v.y = rintf(v.y / fc);
                v.z = rintf(v.z / fc); v.w = rintf(v.w / fc);
                outC[u] = v;
            }
        }
    }
}

// ---------------------------------------------------------------------------

extern "C" void kernel_launch(void* const* d_in, const int* in_sizes, int n_in,
                              void* d_out, int out_size) {
    const int4*  coords = (const int4*)d_in[0];   // [N,4] int32
    const float* feats  = (const float*)d_in[1];  // [N,64] float32
    const int n = in_sizes[0] / 4;

    float* outC = (float*)d_out;                  // [N,4]
    float* outF = outC + (size_t)n * 4;           // [N,64]

    const int TPB = 256;

    k_scanall<<<NBLK, TPB>>>(coords, (float4*)outC, n);
    k_featstore<<<(n + 15) / 16, 256>>>((const float4*)feats, (float4*)outF, n);
    k_residual<<<64, 256>>>(coords, feats, outC, outF);
    k_finalize<<<512, 256>>>((float4*)outC, (float4*)outF);
}